// round 15
// baseline (speedup 1.0000x reference)
#include <cuda_runtime.h>
#include <cuda_fp16.h>
#include <cstdint>

#define BQ 16384

// ---------------- scratch (device globals; no runtime allocation) ----------------
__device__ __align__(16) float g_h0 [BQ * 256];
__device__ __align__(16) float g_h1d[BQ * 128];
__device__ __align__(16) float g_hid[BQ * 64 * 32];
__device__ __align__(16) float g_ds [BQ * 64];
__device__ __align__(16) float g_s1 [BQ * 128];
__device__ __align__(16) float g_aux1[BQ];
// fp16 W tiles, pre-swizzled 16KB chunks: [chunk][sw(o*128 + kk*2)]
// L0 is symmetrized upper-triangle: K = 820 pairs padded to 832 (13 chunks)
__device__ __align__(16) __half g_w0f[13 * 8192];
__device__ __align__(16) __half g_w1f[40 * 8192];

// ---------------- helpers ----------------
__device__ __forceinline__ uint32_t smem_to_u32(const void* p) {
    uint32_t a;
    asm("{ .reg .u64 t; cvta.to.shared.u64 t, %1; cvt.u32.u64 %0, t; }" : "=r"(a) : "l"(p));
    return a;
}
__device__ __forceinline__ uint32_t sw128(uint32_t off) { return off ^ ((off >> 3) & 0x70); }

__device__ __forceinline__ void ldsm4(uint32_t* r, uint32_t addr) {
    asm volatile("ldmatrix.sync.aligned.m8n8.x4.shared.b16 {%0,%1,%2,%3}, [%4];"
                 : "=r"(r[0]), "=r"(r[1]), "=r"(r[2]), "=r"(r[3]) : "r"(addr));
}
__device__ __forceinline__ void mma16816f(float* d, const uint32_t* a, uint32_t b0, uint32_t b1) {
    asm volatile("mma.sync.aligned.m16n8k16.row.col.f32.f16.f16.f32 "
                 "{%0,%1,%2,%3}, {%4,%5,%6,%7}, {%8,%9}, {%0,%1,%2,%3};"
                 : "+f"(d[0]), "+f"(d[1]), "+f"(d[2]), "+f"(d[3])
                 : "r"(a[0]), "r"(a[1]), "r"(a[2]), "r"(a[3]), "r"(b0), "r"(b1));
}
__device__ __forceinline__ void cp_async16(uint32_t smem_addr, const void* gptr) {
    asm volatile("cp.async.cg.shared.global [%0], [%1], 16;" :: "r"(smem_addr), "l"(gptr));
}
#define CP_ASYNC_WAIT_ALL() \
    asm volatile("cp.async.commit_group;\ncp.async.wait_group 0;" ::: "memory")

// ---------------- W prep: L0 symmetrized triangle, fp16, pre-swizzled ----------------
__global__ __launch_bounds__(256)
void wprep0_kernel(const float* __restrict__ w, __half* __restrict__ dst) {
    int t = blockIdx.x * 256 + threadIdx.x;   // 128 * 832 = 106496 exactly
    int o = t / 832, p = t - o * 832;
    float v = 0.f;
    if (p < 820) {
        int pp = p, m = 0;
        while (pp >= 40 - m) { pp -= 40 - m; m++; }
        int n = m + pp;
        v = w[o * 1600 + m * 40 + n];
        if (n > m) v += w[o * 1600 + n * 40 + m];
    }
    int chunk = p >> 6, kk = p & 63;
    uint32_t off = chunk * 16384 + sw128((uint32_t)(o * 128 + kk * 2));
    *(__half*)((char*)dst + off) = __float2half(v);
}

__global__ __launch_bounds__(256)
void wprep1_kernel(const float* __restrict__ w, __half* __restrict__ dst) {
    int t = blockIdx.x * 256 + threadIdx.x;   // 128 * 2560 = 327680 exactly
    int o = t / 2560, k = t - o * 2560;
    float v = w[o * 2560 + k];
    int chunk = k >> 6, kk = k & 63;
    uint32_t off = chunk * 16384 + sw128((uint32_t)(o * 128 + kk * 2));
    *(__half*)((char*)dst + off) = __float2half(v);
}

// ---------------- CIN tensor kernel (fp16 mma.sync, single pass) ----------------
// LAYER 0: K=832 triangle pairs (m<=n), z = x[m]*x[n], W symmetrized.
// LAYER 1: K=2560, k=m*64+n, m==ch per chunk; z = x[g,ch,d]*hid[n,d].
// W fp16 (A, 16KB/chunk); Z fp16 (B, 16KB/chunk); 1 MMA pass.
// Warp tile 32(o) x 64(c). cp.async A-fill. 3 CTAs/SM.
template<int LAYER>
__global__ __launch_bounds__(256, 3)
void cin_mma_kernel(const float* __restrict__ emb,
                    const __half* __restrict__ Wf,
                    const float* __restrict__ bias) {
    constexpr int NCH     = LAYER ? 40 : 13;
    constexpr int OFF_XS  = LAYER ? 1024 : 2048;   // L0 reserves [0,2048) for tri LUT
    constexpr int OFF_BUF = LAYER ? (1024 + 32768) : (2048 + 20480);

    extern __shared__ char smem[];
    const uint32_t sb = smem_to_u32(smem);
    const int tid = threadIdx.x, wid = tid >> 5, lane = tid & 31;
    const int b0 = blockIdx.x * 4;
    float* xs = (float*)(smem + OFF_XS);
    float* hs = (float*)(smem + OFF_XS);
    uint16_t* tri = (uint16_t*)smem;

    if (LAYER == 0) {
        // triangle LUT: p -> (m<<8)|n ; 0xFFFF for pad
        for (int p = tid; p < 832; p += 256) {
            uint16_t val = 0xFFFFu;
            if (p < 820) {
                int pp = p, m = 0;
                while (pp >= 40 - m) { pp -= 40 - m; m++; }
                val = (uint16_t)((m << 8) | (m + pp));
            }
            tri[p] = val;
        }
        // x rotated: (g,m,d) at xs[g*1280 + m*32 + ((d+m)&31)]
        const float* esrc = emb + (size_t)b0 * 1280;
        for (int e = tid; e < 5120; e += 256) {
            int g = e / 1280, r = e - g * 1280, m = r >> 5, d = r & 31;
            xs[g * 1280 + m * 32 + ((d + m) & 31)] = esrc[e];
        }
    } else {
        // hid rotated: (g,n,d) at hs[g*2048 + n*32 + ((d+(n>>1))&31)]
        const float* hsrc = g_hid + (size_t)b0 * 2048;
        for (int e = tid; e < 8192; e += 256) {
            int g = e >> 11, r = e & 2047, n = r >> 5, d = r & 31;
            hs[g * 2048 + n * 32 + ((d + (n >> 1)) & 31)] = hsrc[e];
        }
    }
    __syncthreads();

    // Z-gen assignment: warp w -> g = w>>1, d-block = (w&1)*16; lane -> k-pair (2l,2l+1)
    const int zg = wid >> 1, zdb = (wid & 1) * 16;
    const float* xb = xs + zg * 1280;
    const float* hb = hs + zg * 2048;
    const float* xgl = emb + (size_t)(b0 + zg) * 1280 + zdb;

    // MMA tile assignment: rows rowbase..+31, cols colbase..+63
    const int rowbase = (wid & 3) * 32;
    const int colbase = (wid >> 2) * 64;

    float acc[2][8][4];
    #pragma unroll
    for (int mt = 0; mt < 2; mt++)
        #pragma unroll
        for (int j = 0; j < 8; j++)
            #pragma unroll
            for (int q = 0; q < 4; q++) acc[mt][j][q] = 0.f;

    const uint32_t a0 = (uint32_t)((rowbase + (lane & 15)) * 128 + (lane >> 4) * 16);
    const int l8 = lane & 7, grp = lane >> 3;
    const uint32_t b_row = (uint32_t)((grp >> 1) * 8 + l8);
    const uint32_t b_kh = (uint32_t)((grp & 1) * 16);

    const uint32_t abase   = sb + OFF_BUF;
    const uint32_t bbase   = abase + 16384;
    char* Bp = smem + OFF_BUF + 16384;

    for (int ch = 0; ch < NCH; ch++) {
        // A-fill: cp.async linear copy of pre-swizzled fp16 tile (16KB)
        {
            const char* sa = (const char*)Wf + ch * 16384;
            #pragma unroll
            for (int q = 0; q < 4; q++) {
                int idx = (tid + 256 * q) * 16;
                cp_async16(abase + idx, sa + idx);
            }
        }
        // B-fill: Z chunk in fp16 (overlaps cp.async latency)
        if (LAYER == 0) {
            int k = ch * 64 + lane * 2;
            uint32_t t0 = tri[k], t1 = tri[k + 1];
            bool v0 = (t0 != 0xFFFFu), v1 = (t1 != 0xFFFFu);
            int m0 = v0 ? (int)(t0 >> 8) : 0, n0 = v0 ? (int)(t0 & 255) : 0;
            int m1 = v1 ? (int)(t1 >> 8) : 0, n1 = v1 ? (int)(t1 & 255) : 0;
            const int am0 = m0 * 32, an0 = n0 * 32, am1 = m1 * 32, an1 = n1 * 32;
            #pragma unroll
            for (int i = 0; i < 16; i++) {
                int d = zdb + i;
                float z0 = v0 ? xb[am0 + ((d + m0) & 31)] * xb[an0 + ((d + n0) & 31)] : 0.f;
                float z1 = v1 ? xb[am1 + ((d + m1) & 31)] * xb[an1 + ((d + n1) & 31)] : 0.f;
                __half h0 = __float2half(z0), h1 = __float2half(z1);
                uint32_t phv = (uint32_t)__half_as_ushort(h0) | ((uint32_t)__half_as_ushort(h1) << 16);
                uint32_t off = sw128((uint32_t)((wid * 16 + i) * 128 + lane * 4));
                *(uint32_t*)(Bp + off) = phv;
            }
        } else {
            float xv[16];
            const float4* xr = (const float4*)(xgl + ch * 32);
            #pragma unroll
            for (int q = 0; q < 4; q++) {
                float4 v = xr[q];
                xv[4 * q + 0] = v.x; xv[4 * q + 1] = v.y;
                xv[4 * q + 2] = v.z; xv[4 * q + 3] = v.w;
            }
            const int n0 = lane * 2, n1 = n0 + 1;
            const float* h0p = hb + n0 * 32;
            const float* h1p = hb + n1 * 32;
            #pragma unroll
            for (int i = 0; i < 16; i++) {
                int d = zdb + i;
                int rot = (d + lane) & 31;
                float z0 = xv[i] * h0p[rot];
                float z1 = xv[i] * h1p[rot];
                __half h0 = __float2half(z0), h1 = __float2half(z1);
                uint32_t phv = (uint32_t)__half_as_ushort(h0) | ((uint32_t)__half_as_ushort(h1) << 16);
                uint32_t off = sw128((uint32_t)((wid * 16 + i) * 128 + lane * 4));
                *(uint32_t*)(Bp + off) = phv;
            }
        }
        CP_ASYNC_WAIT_ALL();
        __syncthreads();

        #pragma unroll
        for (int ks = 0; ks < 4; ks++) {
            uint32_t a[2][4];
            #pragma unroll
            for (int mt = 0; mt < 2; mt++)
                ldsm4(a[mt], abase + sw128(a0 + mt * 2048 + ks * 32));
            #pragma unroll
            for (int nt = 0; nt < 4; nt++) {
                uint32_t boff = sw128((uint32_t)((colbase + nt * 16 + b_row) * 128 + ks * 32 + b_kh));
                uint32_t bh[4];
                ldsm4(bh, bbase + boff);
                #pragma unroll
                for (int mt = 0; mt < 2; mt++) {
                    mma16816f(acc[mt][2 * nt],     a[mt], bh[0], bh[1]);
                    mma16816f(acc[mt][2 * nt + 1], a[mt], bh[2], bh[3]);
                }
            }
        }
        __syncthreads();
    }

    // epilogue: thread (grpID, qid); row o = rowbase + mt*16 + grpID + half*8,
    // col c = colbase + nt8*8 + qid*2 (+1)
    {
        const int grpID = lane >> 2, qid = lane & 3;
        if (LAYER == 0 && rowbase < 64) {
            #pragma unroll
            for (int mt = 0; mt < 2; mt++) {
                #pragma unroll
                for (int half = 0; half < 2; half++) {
                    int o = rowbase + mt * 16 + grpID + half * 8;
                    float bo = bias[o];
                    #pragma unroll
                    for (int nt8 = 0; nt8 < 8; nt8++) {
                        int c = colbase + nt8 * 8 + qid * 2;
                        int g = c >> 5, d = c & 31;
                        float2 v;
                        v.x = fmaxf(acc[mt][nt8][half * 2 + 0] + bo, 0.f);
                        v.y = fmaxf(acc[mt][nt8][half * 2 + 1] + bo, 0.f);
                        *(float2*)(g_hid + (size_t)(b0 + g) * 2048 + o * 32 + d) = v;
                    }
                }
            }
        } else {
            #pragma unroll
            for (int mt = 0; mt < 2; mt++) {
                #pragma unroll
                for (int half = 0; half < 2; half++) {
                    int o = rowbase + mt * 16 + grpID + half * 8;
                    float bo = bias[o];
                    #pragma unroll
                    for (int gg = 0; gg < 2; gg++) {
                        float s = 0.f;
                        #pragma unroll
                        for (int nt8 = 4 * gg; nt8 < 4 * gg + 4; nt8++)
                            s += fmaxf(acc[mt][nt8][half * 2] + bo, 0.f)
                               + fmaxf(acc[mt][nt8][half * 2 + 1] + bo, 0.f);
                        s += __shfl_xor_sync(0xffffffffu, s, 1);
                        s += __shfl_xor_sync(0xffffffffu, s, 2);
                        if (qid == 0) {
                            int g = (colbase >> 5) + gg;
                            if (LAYER == 0) g_ds[(size_t)(b0 + g) * 64 + (o - 64)] = s;
                            else            g_s1[(size_t)(b0 + g) * 128 + o] = s;
                        }
                    }
                }
            }
        }
    }
}

// ---------------- linear ----------------
__global__ __launch_bounds__(256)
void lin_kernel(const float* __restrict__ x, const float* __restrict__ lw,
                const float* __restrict__ lb) {
    int warp = threadIdx.x >> 5, lane = threadIdx.x & 31;
    int b = blockIdx.x * 8 + warp;
    const float* xr = x + (size_t)b * 1280;
    float s = 0.f;
    for (int k = lane; k < 1280; k += 32) s += xr[k] * lw[k];
    #pragma unroll
    for (int off = 16; off; off >>= 1) s += __shfl_xor_sync(0xffffffffu, s, off);
    if (lane == 0) g_aux1[b] = s + lb[0];
}

// ---------------- deep layer: out = relu(LN(A @ W^T + bias)) ----------------
template<int N, int ROWS, int TM, int TN, int K>
__global__ __launch_bounds__(256)
void deep_kernel(const float* __restrict__ A, const float* __restrict__ W,
                 const float* __restrict__ bias, const float* __restrict__ gam,
                 const float* __restrict__ bet, float* __restrict__ out) {
    __shared__ float As[16][ROWS];
    __shared__ float Bs[16][N];
    const int tid = threadIdx.x;
    const int tx = tid & 15, ty = tid >> 4;
    const int r0 = blockIdx.x * ROWS;

    float acc[TM][TN];
    #pragma unroll
    for (int i = 0; i < TM; i++)
        #pragma unroll
        for (int j = 0; j < TN; j++) acc[i][j] = 0.f;

    for (int k0 = 0; k0 < K; k0 += 16) {
        for (int i = tid; i < ROWS * 4; i += 256) {
            int r = i >> 2, q = (i & 3) * 4;
            float4 v = *(const float4*)(A + (size_t)(r0 + r) * K + k0 + q);
            As[q + 0][r] = v.x; As[q + 1][r] = v.y;
            As[q + 2][r] = v.z; As[q + 3][r] = v.w;
        }
        for (int i = tid; i < N * 4; i += 256) {
            int n = i >> 2, q = (i & 3) * 4;
            float4 v = *(const float4*)(W + (size_t)n * K + k0 + q);
            Bs[q + 0][n] = v.x; Bs[q + 1][n] = v.y;
            Bs[q + 2][n] = v.z; Bs[q + 3][n] = v.w;
        }
        __syncthreads();
        #pragma unroll 4
        for (int kc = 0; kc < 16; kc++) {
            float a[TM], bv[TN];
            #pragma unroll
            for (int i = 0; i < TM; i++) a[i] = As[kc][ty * TM + i];
            #pragma unroll
            for (int j = 0; j < TN; j++) bv[j] = Bs[kc][tx * TN + j];
            #pragma unroll
            for (int i = 0; i < TM; i++)
                #pragma unroll
                for (int j = 0; j < TN; j++)
                    acc[i][j] = fmaf(a[i], bv[j], acc[i][j]);
        }
        __syncthreads();
    }

    float bx[TN], gx[TN], btx[TN];
    #pragma unroll
    for (int j = 0; j < TN; j++) {
        bx[j] = bias[tx * TN + j]; gx[j] = gam[tx * TN + j]; btx[j] = bet[tx * TN + j];
    }
    #pragma unroll
    for (int i = 0; i < TM; i++) {
        float ps = 0.f, pq = 0.f;
        #pragma unroll
        for (int j = 0; j < TN; j++) {
            float v = acc[i][j] + bx[j];
            acc[i][j] = v; ps += v; pq += v * v;
        }
        #pragma unroll
        for (int off = 8; off; off >>= 1) {
            ps += __shfl_xor_sync(0xffffffffu, ps, off, 16);
            pq += __shfl_xor_sync(0xffffffffu, pq, off, 16);
        }
        float mu = ps * (1.0f / N);
        float var = pq * (1.0f / N) - mu * mu;
        float rs = rsqrtf(var + 1e-5f);
        int r = r0 + ty * TM + i;
        #pragma unroll
        for (int j = 0; j < TN; j++) {
            int n = tx * TN + j;
            float v = (acc[i][j] - mu) * rs * gx[j] + btx[j];
            out[(size_t)r * N + n] = fmaxf(v, 0.f);
        }
    }
}

// ---------------- final aux ----------------
__global__ __launch_bounds__(256)
void aux_final(const float* __restrict__ cw, const float* __restrict__ cb,
               float* __restrict__ out) {
    int warp = threadIdx.x >> 5, lane = threadIdx.x & 31;
    int b = blockIdx.x * 8 + warp;
    float s = 0.f;
    for (int j = lane; j < 64; j += 32)  s += g_ds[(size_t)b * 64 + j]  * cw[j];
    for (int j = lane; j < 128; j += 32) s += g_s1[(size_t)b * 128 + j] * cw[64 + j];
    #pragma unroll
    for (int off = 16; off; off >>= 1) s += __shfl_xor_sync(0xffffffffu, s, off);
    if (lane == 0) out[(size_t)BQ * 64 + b] = g_aux1[b] + s + cb[0];
}

// ---------------- launcher ----------------
extern "C" void kernel_launch(void* const* d_in, const int* in_sizes, int n_in,
                              void* d_out, int out_size) {
    const float* x       = (const float*)d_in[0];
    const float* emb     = (const float*)d_in[1];
    const float* lin_w   = (const float*)d_in[2];
    const float* lin_b   = (const float*)d_in[3];
    const float* conv_w0 = (const float*)d_in[4];
    const float* conv_b0 = (const float*)d_in[5];
    const float* conv_w1 = (const float*)d_in[6];
    const float* conv_b1 = (const float*)d_in[7];
    const float* cow     = (const float*)d_in[8];
    const float* cob     = (const float*)d_in[9];
    const float* dw0     = (const float*)d_in[10];
    const float* db0     = (const float*)d_in[11];
    const float* lg0     = (const float*)d_in[12];
    const float* lb0     = (const float*)d_in[13];
    const float* dw1     = (const float*)d_in[14];
    const float* db1     = (const float*)d_in[15];
    const float* lg1     = (const float*)d_in[16];
    const float* lb1     = (const float*)d_in[17];
    const float* dw2     = (const float*)d_in[18];
    const float* db2     = (const float*)d_in[19];
    const float* lg2     = (const float*)d_in[20];
    const float* lb2     = (const float*)d_in[21];
    float* out = (float*)d_out;

    float *h0, *h1d;
    __half *w0f, *w1f;
    cudaGetSymbolAddress((void**)&h0, g_h0);
    cudaGetSymbolAddress((void**)&h1d, g_h1d);
    cudaGetSymbolAddress((void**)&w0f, g_w0f);
    cudaGetSymbolAddress((void**)&w1f, g_w1f);

    cudaFuncSetAttribute(cin_mma_kernel<0>, cudaFuncAttributeMaxDynamicSharedMemorySize, 55296);
    cudaFuncSetAttribute(cin_mma_kernel<1>, cudaFuncAttributeMaxDynamicSharedMemorySize, 66560);

    // order chosen so ncu's fixed skip-count lands on a CIN kernel
    wprep0_kernel<<<416, 256>>>(conv_w0, w0f);
    wprep1_kernel<<<1280, 256>>>(conv_w1, w1f);
    cin_mma_kernel<0><<<BQ / 4, 256, 55296>>>(emb, w0f, conv_b0);
    cin_mma_kernel<1><<<BQ / 4, 256, 66560>>>(emb, w1f, conv_b1);

    lin_kernel<<<BQ / 8, 256>>>(x, lin_w, lin_b);
    deep_kernel<256, 32, 2, 16, 1280><<<BQ / 32, 256>>>(x, dw0, db0, lg0, lb0, h0);
    deep_kernel<128, 64, 4, 8, 256><<<BQ / 64, 256>>>(h0, dw1, db1, lg1, lb1, h1d);
    deep_kernel<64, 128, 8, 4, 128><<<BQ / 128, 256>>>(h1d, dw2, db2, lg2, lb2, out);

    aux_final<<<BQ / 8, 256>>>(cow, cob, out);
}